// round 2
// baseline (speedup 1.0000x reference)
#include <cuda_runtime.h>
#include <cstdint>

// ==================== problem sizes ====================
#define B_DIM 4096
#define H_DIM 2048
#define K_DIM 4096      // I + H
#define N4    8192      // 4*H

// ==================== tiling ====================
#define BM 128          // batch rows per CTA
#define BJ 64           // per-gate H columns per CTA
#define BN 256          // total N columns per CTA = 4 gates * BJ
#define BK 32           // K per stage
#define STAGES 4
#define NIT (K_DIM / BK)      // 128

#define A_WORDS (BM * BK)             // 4096 floats = 16KB
#define B_WORDS (BK * BN)             // 8192 floats = 32KB
#define STG_WORDS (A_WORDS + B_WORDS) // 12288
#define SMEM_BYTES (STAGES * STG_WORDS * 4)  // 196608

// ==================== helpers ====================
__device__ __forceinline__ uint32_t smem_u32(const void* p) {
    uint32_t a;
    asm("{ .reg .u64 t; cvta.to.shared.u64 t, %1; cvt.u32.u64 %0, t; }" : "=r"(a) : "l"(p));
    return a;
}
__device__ __forceinline__ uint32_t f2tf32(float f) {
    uint32_t r;
    asm("cvt.rna.tf32.f32 %0, %1;" : "=r"(r) : "f"(f));
    return r;
}
#define CP16(dst, src) asm volatile("cp.async.cg.shared.global [%0], [%1], 16;" :: "r"(dst), "l"(src))
#define CP_COMMIT()    asm volatile("cp.async.commit_group;" ::: "memory")
#define CP_WAIT(n)     asm volatile("cp.async.wait_group %0;" :: "n"(n) : "memory")

#define MMA_TF32(d, a, b)                                                        \
    asm volatile("mma.sync.aligned.m16n8k8.row.col.f32.tf32.tf32.f32 "           \
                 "{%0,%1,%2,%3}, {%4,%5,%6,%7}, {%8,%9}, {%0,%1,%2,%3};"         \
                 : "+f"((d)[0]), "+f"((d)[1]), "+f"((d)[2]), "+f"((d)[3])        \
                 : "r"((a)[0]), "r"((a)[1]), "r"((a)[2]), "r"((a)[3]),           \
                   "r"((b)[0]), "r"((b)[1]))

extern __shared__ float smem[];

// ==================== fused GEMM + sLSTM kernel ====================
__global__ __launch_bounds__(256, 1)
void slstm_mma(const float* __restrict__ x, const float* __restrict__ h,
               const float* __restrict__ c_in, const float* __restrict__ n_in,
               const float* __restrict__ m_in, const float* __restrict__ W,
               const float* __restrict__ bias, float* __restrict__ out)
{
    const int tid = threadIdx.x;
    const int wid = tid >> 5, lane = tid & 31;
    const int gID = lane >> 2, tg = lane & 3;       // mma group / thread-in-group
    const int warpM = wid >> 2, warpN = wid & 3;    // 2 x 4 warp grid, warp tile 64x64
    const int m0 = (blockIdx.x & 31) * BM;          // 32 m-tiles
    const int jb = (blockIdx.x >> 5) * BJ;          // 32 j-tiles

    const uint32_t sbase = smem_u32(smem);

    float acc[4][8][4];
#pragma unroll
    for (int a = 0; a < 4; a++)
#pragma unroll
        for (int b = 0; b < 8; b++)
#pragma unroll
            for (int c = 0; c < 4; c++) acc[a][b][c] = 0.f;

    // ---- stage loader: A[128 x 32] from x/h, B[32 x 256] = 4 gate slices of W ----
    auto load_stage = [&](int slot, int k0) {
        const uint32_t abase = sbase + (uint32_t)(slot * (STG_WORDS * 4));
        // A tile: rows m (batch), cols k. BK=32 tile lies fully in x or h.
        const float* asrc = (k0 < H_DIM) ? (x + (size_t)m0 * H_DIM + k0)
                                         : (h + (size_t)m0 * H_DIM + (k0 - H_DIM));
#pragma unroll
        for (int i = 0; i < 4; i++) {
            const int cidx = tid + 256 * i;          // chunk id 0..1023
            const int am = cidx >> 3, ach = cidx & 7;
            const uint32_t dst = abase +
                (uint32_t)(((am * BK) + ((ach ^ (am & 7)) << 2)) << 2);
            CP16(dst, asrc + (size_t)am * H_DIM + (ach << 2));
        }
        const uint32_t bbase = abase + A_WORDS * 4;
        const float* bsrc = W + (size_t)k0 * N4;
#pragma unroll
        for (int i = 0; i < 8; i++) {
            const int cidx = tid + 256 * i;          // chunk id 0..2047
            const int bk = cidx >> 6, ch = cidx & 63;
            const int w = ch << 2;
            const int wsw = w ^ ((bk & 3) << 3);     // swizzle: conflict-free frag loads
            const uint32_t dst = bbase + (uint32_t)(((bk * BN) + wsw) << 2);
            // SMEM col cn -> gmem col: q=cn>>5, gate=(cn>>3)&3, u=cn&7
            const int cn = ch << 2;
            const int q = cn >> 5, g = (cn >> 3) & 3, u = cn & 7;
            CP16(dst, bsrc + (size_t)bk * N4 + (g * H_DIM + jb + q * 8 + u));
        }
    };

    // ---- pipeline prologue ----
#pragma unroll
    for (int s = 0; s < STAGES - 1; s++) {
        load_stage(s, s * BK);
        CP_COMMIT();
    }

    // per-thread invariant fragment addressing
    int rowword[4][2];   // A word base per (mt, r2): m*BK + tg
#pragma unroll
    for (int mt = 0; mt < 4; mt++) {
#pragma unroll
        for (int r2 = 0; r2 < 2; r2++)
            rowword[mt][r2] = (warpM * 64 + mt * 16 + gID + 8 * r2) * BK + tg;
    }
    int nsw[8];          // swizzled B column per n-tile
#pragma unroll
    for (int nt = 0; nt < 8; nt++)
        nsw[nt] = (warpN * 64 + nt * 8 + gID) ^ (tg << 3);

    // ---- main loop ----
    for (int it = 0; it < NIT; ++it) {
        CP_WAIT(STAGES - 2);
        __syncthreads();

        const int nx = it + STAGES - 1;
        if (nx < NIT) load_stage(nx & (STAGES - 1), nx * BK);
        CP_COMMIT();

        const float* As = smem + (it & (STAGES - 1)) * STG_WORDS;
        const float* Bs = As + A_WORDS;

#pragma unroll
        for (int ks = 0; ks < 4; ks++) {
            uint32_t ar[4][4];
#pragma unroll
            for (int mt = 0; mt < 4; mt++) {
#pragma unroll
                for (int hf = 0; hf < 2; hf++) {
                    const int chx = ((2 * ks + hf) ^ gID) << 2;
                    ar[mt][hf * 2 + 0] = f2tf32(As[rowword[mt][0] + chx]);
                    ar[mt][hf * 2 + 1] = f2tf32(As[rowword[mt][1] + chx]);
                }
            }
            uint32_t br[8][2];
#pragma unroll
            for (int nt = 0; nt < 8; nt++) {
                br[nt][0] = f2tf32(Bs[(ks * 8 + tg) * BN + nsw[nt]]);
                br[nt][1] = f2tf32(Bs[(ks * 8 + tg + 4) * BN + nsw[nt]]);
            }
#pragma unroll
            for (int mt = 0; mt < 4; mt++)
#pragma unroll
                for (int nt = 0; nt < 8; nt++)
                    MMA_TF32(acc[mt][nt], ar[mt], br[nt]);
        }
        __syncthreads();
    }

    // ---- fused sLSTM epilogue (pure registers) ----
    const size_t plane = (size_t)B_DIM * H_DIM;

    float bz[2][2], bi[2][2], bfv[2][2], bo[2][2];
#pragma unroll
    for (int q = 0; q < 2; q++) {
        const int j = jb + (2 * warpN + q) * 8 + 2 * tg;
#pragma unroll
        for (int e = 0; e < 2; e++) {
            bz[q][e]  = bias[j + e];
            bi[q][e]  = bias[H_DIM + j + e];
            bfv[q][e] = bias[2 * H_DIM + j + e];
            bo[q][e]  = bias[3 * H_DIM + j + e];
        }
    }

#pragma unroll
    for (int mt = 0; mt < 4; mt++) {
#pragma unroll
        for (int r2 = 0; r2 < 2; r2++) {
            const int m = m0 + warpM * 64 + mt * 16 + gID + 8 * r2;
#pragma unroll
            for (int q = 0; q < 2; q++) {
                const int j = jb + (2 * warpN + q) * 8 + 2 * tg;
                const size_t off = (size_t)m * H_DIM + j;
                const float2 cv = *(const float2*)(c_in + off);
                const float2 nv = *(const float2*)(n_in + off);
                const float2 mv = *(const float2*)(m_in + off);
                float2 ho, co, no, mo;
#pragma unroll
                for (int e = 0; e < 2; e++) {
                    const float zt  = acc[mt][q * 4 + 0][r2 * 2 + e] + bz[q][e];
                    const float it_ = acc[mt][q * 4 + 1][r2 * 2 + e] + bi[q][e];
                    const float ft  = acc[mt][q * 4 + 2][r2 * 2 + e] + bfv[q][e];
                    const float ot  = acc[mt][q * 4 + 3][r2 * 2 + e] + bo[q][e];

                    const float zv = tanhf(zt);
                    const float ef = __expf(-fabsf(ft));
                    const float rf = 1.f / (1.f + ef);
                    const float sf = (ft >= 0.f) ? rf : ef * rf;        // sigmoid(f)
                    const float logsig = fminf(ft, 0.f) - log1pf(ef);   // log sigmoid(f)
                    const float eo = __expf(-fabsf(ot));
                    const float ro = 1.f / (1.f + eo);
                    const float so = (ot >= 0.f) ? ro : eo * ro;        // sigmoid(o)

                    const float m_old = e ? mv.y : mv.x;
                    const float mt_ = fmaxf(logsig + m_old, it_);
                    const float ip = __expf(it_ - mt_);
                    const float ct = sf * (e ? cv.y : cv.x) + ip * zv;
                    const float ntv = sf * (e ? nv.y : nv.x) + ip;
                    const float htv = so * (ct / ntv);

                    *(e ? &ho.y : &ho.x) = htv;
                    *(e ? &co.y : &co.x) = ct;
                    *(e ? &no.y : &no.x) = ntv;
                    *(e ? &mo.y : &mo.x) = mt_;
                }
                *(float2*)(out + off)             = ho;
                *(float2*)(out + plane + off)     = co;
                *(float2*)(out + 2 * plane + off) = no;
                *(float2*)(out + 3 * plane + off) = mo;
            }
        }
    }
}

// ==================== host launch ====================
extern "C" void kernel_launch(void* const* d_in, const int* in_sizes, int n_in,
                              void* d_out, int out_size) {
    (void)in_sizes; (void)n_in; (void)out_size;
    const float* x    = (const float*)d_in[0];
    const float* h    = (const float*)d_in[1];
    const float* c    = (const float*)d_in[2];
    const float* n    = (const float*)d_in[3];
    const float* m    = (const float*)d_in[4];
    const float* W    = (const float*)d_in[5];
    const float* bias = (const float*)d_in[6];
    float* out = (float*)d_out;

    cudaFuncSetAttribute(slstm_mma, cudaFuncAttributeMaxDynamicSharedMemorySize, SMEM_BYTES);
    slstm_mma<<<(B_DIM / BM) * (H_DIM / BJ), 256, SMEM_BYTES>>>(
        x, h, c, n, m, W, bias, out);
}

// round 3
// speedup vs baseline: 1.2666x; 1.2666x over previous
#include <cuda_runtime.h>
#include <cstdint>

// ==================== problem sizes ====================
#define B_DIM 4096
#define H_DIM 2048
#define K_DIM 4096      // I + H
#define N4    8192      // 4*H

// ==================== tiling ====================
#define BM 128          // batch rows per CTA
#define BJ 64           // per-gate H columns per CTA
#define BN 256          // 4 gates * BJ
#define BK 32           // K per stage
#define STAGES 4
#define NIT (K_DIM / BK)              // 128

#define A_STG_WORDS 4096              // 64 m2 * 16 k2 * 4  (16KB)
#define B_STG_WORDS 8192              // 16 k2 * 256 cn * 2 (32KB)
#define STG_WORDS  (A_STG_WORDS + B_STG_WORDS)
#define STG_BYTES  (STG_WORDS * 4)    // 49152
#define SMEM_BYTES (STAGES * STG_BYTES)  // 196608

// scratch: tf32-pre-rounded, fragment-ordered, swizzled SMEM images
__device__ float g_Ap[(size_t)32 * 128 * A_STG_WORDS];   // [m_tile][k_stage][4096]
__device__ float g_Wp[(size_t)32 * 128 * B_STG_WORDS];   // [j_tile][k_stage][8192]

// ==================== helpers ====================
__device__ __forceinline__ uint32_t smem_u32(const void* p) {
    uint32_t a;
    asm("{ .reg .u64 t; cvta.to.shared.u64 t, %1; cvt.u32.u64 %0, t; }" : "=r"(a) : "l"(p));
    return a;
}
__device__ __forceinline__ float f2tf32(float f) {
    uint32_t r;
    asm("cvt.rna.tf32.f32 %0, %1;" : "=r"(r) : "f"(f));
    return __uint_as_float(r);
}
#define CP16(dst, src) asm volatile("cp.async.cg.shared.global [%0], [%1], 16;" :: "r"(dst), "l"(src))
#define CP_COMMIT()    asm volatile("cp.async.commit_group;" ::: "memory")
#define CP_WAIT(n)     asm volatile("cp.async.wait_group %0;" :: "n"(n) : "memory")

#define MMA_TF32(d, a, b)                                                        \
    asm volatile("mma.sync.aligned.m16n8k8.row.col.f32.tf32.tf32.f32 "           \
                 "{%0,%1,%2,%3}, {%4,%5,%6,%7}, {%8,%9}, {%0,%1,%2,%3};"         \
                 : "+f"((d)[0]), "+f"((d)[1]), "+f"((d)[2]), "+f"((d)[3])        \
                 : "r"((a)[0]), "r"((a)[1]), "r"((a)[2]), "r"((a)[3]),           \
                   "r"((b)[0]), "r"((b)[1]))

#define LDS128(r, addr)                                                          \
    asm volatile("ld.shared.v4.u32 {%0,%1,%2,%3}, [%4];"                         \
                 : "=r"((r)[0]), "=r"((r)[1]), "=r"((r)[2]), "=r"((r)[3]) : "r"(addr))
#define LDS64(r, addr)                                                           \
    asm volatile("ld.shared.v2.u32 {%0,%1}, [%2];"                               \
                 : "=r"((r)[0]), "=r"((r)[1]) : "r"(addr))

// ==================== prepass: A = [x|h] -> quad-fragment tf32 layout ====================
// quad q of (m2,k2): {(m,k),(m+8,k),(m,k+4),(m+8,k+4)}, m2=(blk16<<3)+row, k2=ks*4+tg
// stored at word (m2*16 + (k2 ^ ((m2&3)<<2)))*4 + q
__global__ __launch_bounds__(256) void prep_A(const float* __restrict__ x,
                                              const float* __restrict__ h) {
    __shared__ float t[128 * 32];
    const int kst = blockIdx.x, mt = blockIdx.y;
    const int tid = threadIdx.x;
#pragma unroll
    for (int j = 0; j < 16; j++) {
        const int i = tid + 256 * j;
        const int ml = i >> 5, kl = i & 31;
        const int kg = kst * 32 + kl;
        t[i] = (kg < H_DIM) ? x[(size_t)(mt * 128 + ml) * H_DIM + kg]
                            : h[(size_t)(mt * 128 + ml) * H_DIM + (kg - H_DIM)];
    }
    __syncthreads();
    float* outp = g_Ap + ((size_t)mt * 128 + kst) * A_STG_WORDS;
#pragma unroll
    for (int j = 0; j < 16; j++) {
        const int w = tid + 256 * j;
        const int q = w & 3, k2s = (w >> 2) & 15, m2 = w >> 6;
        const int k2 = k2s ^ ((m2 & 3) << 2);
        const int ml = ((m2 >> 3) << 4) + (m2 & 7) + ((q & 1) << 3);
        const int kl = ((k2 >> 2) << 3) + (k2 & 3) + ((q & 2) << 1);
        outp[w] = f2tf32(t[ml * 32 + kl]);
    }
}

// ==================== prepass: W -> pair-fragment, gate-interleaved tf32 layout ====================
// pair p of (k2,cn): rows 8*(k2>>2)+(k2&3)+4p, col cn -> gate (cn>>3)&3, j = jt*64+((cn>>5)<<3)+(cn&7)
// stored at word (k2*256 + (cn ^ ((k2&3)<<3)))*2 + p
__global__ __launch_bounds__(256) void prep_W(const float* __restrict__ W) {
    __shared__ float t[32 * 256];
    const int kst = blockIdx.x, jt = blockIdx.y;
    const int tid = threadIdx.x;
#pragma unroll
    for (int j = 0; j < 32; j++) {
        const int i = tid + 256 * j;
        const int kl = i >> 8, sc = i & 255;
        const int col = (sc >> 6) * H_DIM + jt * 64 + (sc & 63);
        t[i] = W[(size_t)(kst * 32 + kl) * N4 + col];
    }
    __syncthreads();
    float* outp = g_Wp + ((size_t)jt * 128 + kst) * B_STG_WORDS;
#pragma unroll
    for (int j = 0; j < 32; j++) {
        const int w = tid + 256 * j;
        const int p = w & 1, cns = (w >> 1) & 255, k2 = w >> 9;
        const int cn = cns ^ ((k2 & 3) << 3);
        const int g = (cn >> 3) & 3;
        const int jl = ((cn >> 5) << 3) | (cn & 7);
        const int kl = ((k2 >> 2) << 3) + (k2 & 3) + (p << 2);
        outp[w] = f2tf32(t[kl * 256 + g * 64 + jl]);
    }
}

extern __shared__ float smem[];

// ==================== fused GEMM + sLSTM kernel ====================
__global__ __launch_bounds__(256, 1)
void slstm_mma(const float* __restrict__ c_in, const float* __restrict__ n_in,
               const float* __restrict__ m_in, const float* __restrict__ bias,
               float* __restrict__ out)
{
    const int tid = threadIdx.x;
    const int wid = tid >> 5, lane = tid & 31;
    const int gID = lane >> 2, tg = lane & 3;
    const int warpM = wid >> 2, warpN = wid & 3;     // 2 x 4 warp grid, 64x64 tiles
    const int mtile = blockIdx.x & 31;
    const int jt = blockIdx.x >> 5;
    const int m0 = mtile * BM, jb = jt * BJ;

    const uint32_t sbase = smem_u32(smem);

    float acc[4][8][4];
#pragma unroll
    for (int a = 0; a < 4; a++)
#pragma unroll
        for (int b = 0; b < 8; b++)
#pragma unroll
            for (int c = 0; c < 4; c++) acc[a][b][c] = 0.f;

    const float* srcAbase = g_Ap + (size_t)mtile * 128 * A_STG_WORDS;
    const float* srcBbase = g_Wp + (size_t)jt * 128 * B_STG_WORDS;

    auto load_stage = [&](int slot, int s) {
        const uint32_t ab = sbase + (uint32_t)(slot * STG_BYTES);
        const float* sa = srcAbase + (size_t)s * A_STG_WORDS;
#pragma unroll
        for (int i = 0; i < 4; i++) {
            const int c = tid + 256 * i;
            CP16(ab + c * 16, sa + c * 4);
        }
        const uint32_t bb = ab + A_STG_WORDS * 4;
        const float* sb = srcBbase + (size_t)s * B_STG_WORDS;
#pragma unroll
        for (int i = 0; i < 8; i++) {
            const int c = tid + 256 * i;
            CP16(bb + c * 16, sb + c * 4);
        }
    };

#pragma unroll
    for (int s = 0; s < STAGES - 1; s++) {
        load_stage(s, s);
        CP_COMMIT();
    }

    // invariant addressing
    uint32_t aoff[4];
#pragma unroll
    for (int mt = 0; mt < 4; mt++)
        aoff[mt] = (uint32_t)(((warpM * 4 + mt) * 8 + gID) * 256);   // bytes
    const uint32_t axr = (uint32_t)((gID & 3) << 2);
    uint32_t boff[8];
#pragma unroll
    for (int nt = 0; nt < 8; nt++)
        boff[nt] = (uint32_t)(tg * 2048 + (((warpN * 64 + nt * 8 + gID) ^ (tg << 3)) << 3));

    for (int it = 0; it < NIT; ++it) {
        CP_WAIT(STAGES - 2);
        __syncthreads();

        const int nx = it + STAGES - 1;
        if (nx < NIT) load_stage(nx & (STAGES - 1), nx);
        CP_COMMIT();

        const uint32_t As = sbase + (uint32_t)((it & (STAGES - 1)) * STG_BYTES);
        const uint32_t Bs = As + A_STG_WORDS * 4;

#pragma unroll
        for (int ks = 0; ks < 4; ks++) {
            const uint32_t kpart = (uint32_t)(((ks * 4 + tg) ^ axr) << 4);
            uint32_t ar[4][4];
#pragma unroll
            for (int mt = 0; mt < 4; mt++)
                LDS128(ar[mt], As + aoff[mt] + kpart);
            uint32_t br[8][2];
#pragma unroll
            for (int nt = 0; nt < 8; nt++)
                LDS64(br[nt], Bs + (uint32_t)(ks * 8192) + boff[nt]);
#pragma unroll
            for (int mt = 0; mt < 4; mt++)
#pragma unroll
                for (int nt = 0; nt < 8; nt++)
                    MMA_TF32(acc[mt][nt], ar[mt], br[nt]);
        }
    }

    // ---- fused sLSTM epilogue ----
    const size_t plane = (size_t)B_DIM * H_DIM;

    float bz[2][2], bi[2][2], bfv[2][2], bo[2][2];
#pragma unroll
    for (int q = 0; q < 2; q++) {
        const int j = jb + (2 * warpN + q) * 8 + 2 * tg;
#pragma unroll
        for (int e = 0; e < 2; e++) {
            bz[q][e]  = bias[j + e];
            bi[q][e]  = bias[H_DIM + j + e];
            bfv[q][e] = bias[2 * H_DIM + j + e];
            bo[q][e]  = bias[3 * H_DIM + j + e];
        }
    }

#pragma unroll
    for (int mt = 0; mt < 4; mt++) {
#pragma unroll
        for (int r2 = 0; r2 < 2; r2++) {
            const int m = m0 + warpM * 64 + mt * 16 + gID + 8 * r2;
#pragma unroll
            for (int q = 0; q < 2; q++) {
                const int j = jb + (2 * warpN + q) * 8 + 2 * tg;
                const size_t off = (size_t)m * H_DIM + j;
                const float2 cv = *(const float2*)(c_in + off);
                const float2 nv = *(const float2*)(n_in + off);
                const float2 mv = *(const float2*)(m_in + off);
                float2 ho, co, no, mo;
#pragma unroll
                for (int e = 0; e < 2; e++) {
                    const float zt  = acc[mt][q * 4 + 0][r2 * 2 + e] + bz[q][e];
                    const float it_ = acc[mt][q * 4 + 1][r2 * 2 + e] + bi[q][e];
                    const float ft  = acc[mt][q * 4 + 2][r2 * 2 + e] + bfv[q][e];
                    const float ot  = acc[mt][q * 4 + 3][r2 * 2 + e] + bo[q][e];

                    const float zv = tanhf(zt);
                    const float ef = __expf(-fabsf(ft));
                    const float rf = 1.f / (1.f + ef);
                    const float sf = (ft >= 0.f) ? rf : ef * rf;        // sigmoid(f)
                    const float logsig = fminf(ft, 0.f) - log1pf(ef);   // log sigmoid(f)
                    const float eo = __expf(-fabsf(ot));
                    const float ro = 1.f / (1.f + eo);
                    const float so = (ot >= 0.f) ? ro : eo * ro;        // sigmoid(o)

                    const float m_old = e ? mv.y : mv.x;
                    const float mt_ = fmaxf(logsig + m_old, it_);
                    const float ip = __expf(it_ - mt_);
                    const float ct = sf * (e ? cv.y : cv.x) + ip * zv;
                    const float ntv = sf * (e ? nv.y : nv.x) + ip;
                    const float htv = so * (ct / ntv);

                    *(e ? &ho.y : &ho.x) = htv;
                    *(e ? &co.y : &co.x) = ct;
                    *(e ? &no.y : &no.x) = ntv;
                    *(e ? &mo.y : &mo.x) = mt_;
                }
                *(float2*)(out + off)             = ho;
                *(float2*)(out + plane + off)     = co;
                *(float2*)(out + 2 * plane + off) = no;
                *(float2*)(out + 3 * plane + off) = mo;
            }
        }
    }
}

// ==================== host launch ====================
extern "C" void kernel_launch(void* const* d_in, const int* in_sizes, int n_in,
                              void* d_out, int out_size) {
    (void)in_sizes; (void)n_in; (void)out_size;
    const float* x    = (const float*)d_in[0];
    const float* h    = (const float*)d_in[1];
    const float* c    = (const float*)d_in[2];
    const float* n    = (const float*)d_in[3];
    const float* m    = (const float*)d_in[4];
    const float* W    = (const float*)d_in[5];
    const float* bias = (const float*)d_in[6];
    float* out = (float*)d_out;

    prep_A<<<dim3(128, 32), 256>>>(x, h);
    prep_W<<<dim3(128, 32), 256>>>(W);

    cudaFuncSetAttribute(slstm_mma, cudaFuncAttributeMaxDynamicSharedMemorySize, SMEM_BYTES);
    slstm_mma<<<(B_DIM / BM) * (H_DIM / BJ), 256, SMEM_BYTES>>>(c, n, m, bias, out);
}